// round 1
// baseline (speedup 1.0000x reference)
#include <cuda_runtime.h>
#include <math.h>

// Tile / problem constants
#define TM      128        // nodes per block
#define SA_LD   68         // padded smem row stride (floats), 16B-aligned, conflict-free
#define KNB     27         // neighbors
#define CLAMP_C 1.0f
#define MAXN    150000

// Scratch for the hidden activations of the two branches (g / h).
__device__ float g_hg[(size_t)MAXN * 64];
__device__ float g_hh[(size_t)MAXN * 64];

__device__ __forceinline__ float lrelu(float v) { return v >= 0.f ? v : 0.2f * v; }

// ---------------------------------------------------------------------------
// Kernel A: for both branches b in {g, h}:
//   hidden_b = lrelu( lrelu( sum_k gather(src, idx_k) @ W1_b[k] ) @ W2_b )
// The gather of `src` is SHARED between the two branches (same indices/source).
// src has row stride src_ld (floats); outputs are dense N x 64.
// ---------------------------------------------------------------------------
__global__ __launch_bounds__(256, 2)
void kconvA(const float* __restrict__ src, int src_ld,
            const int* __restrict__ idx,
            const float* __restrict__ w1g, const float* __restrict__ w2g,
            const float* __restrict__ w1h, const float* __restrict__ w2h,
            float* __restrict__ outg, float* __restrict__ outh, int N)
{
    extern __shared__ float sm[];
    float* sA = sm;                     // TM*SA_LD : gathered tile / hidden_g
    float* sB = sm + TM * SA_LD;        // TM*SA_LD : hidden_h staging
    float* sW = sm + 2 * TM * SA_LD;    // 2*4096  : W1 tile (g then h)

    const int t    = threadIdx.x;
    const int lane = t & 31;
    const int warp = t >> 5;
    const int b    = warp >> 2;         // 0 = g branch, 1 = h branch
    const int wl   = warp & 3;
    const int c0   = (lane & 7) * 8;    // 8 channels per thread
    const int g    = lane >> 3;         // node sub-index (0..3)
    const int n0   = wl * 32 + g;       // thread's nodes: n0 + i*4, i=0..7
    const int nbase = blockIdx.x * TM;

    // Gather mapping: 2 threads per row, 8 float4 each
    const int gr = t >> 1;
    const int gh = t & 1;

    int gn = nbase + gr;
    if (gn >= N) gn = N - 1;
    const int* idxRow = idx + (size_t)gn * KNB;

    float acc[8][8];
#pragma unroll
    for (int i = 0; i < 8; ++i)
#pragma unroll
        for (int q = 0; q < 8; ++q) acc[i][q] = 0.f;

    const float* sWb = sW + b * 4096;

    for (int k = 0; k < KNB; ++k) {
        __syncthreads();
        // Stage W1[k] for both branches (coalesced float4)
        {
            const float4* wg4 = (const float4*)(w1g + (size_t)k * 4096);
            const float4* wh4 = (const float4*)(w1h + (size_t)k * 4096);
            float4* sg4 = (float4*)sW;
            float4* sh4 = (float4*)(sW + 4096);
#pragma unroll
            for (int i = 0; i < 4; ++i) {
                sg4[t + i * 256] = wg4[t + i * 256];
                sh4[t + i * 256] = wh4[t + i * 256];
            }
        }
        // Gather 128 neighbor rows (64 floats each) into sA
        {
            const int row = idxRow[k];
            const float4* s4 = (const float4*)(src + (size_t)row * src_ld) + gh * 8;
            float4* d4 = (float4*)(sA + gr * SA_LD) + gh * 8;
#pragma unroll
            for (int p = 0; p < 8; ++p) d4[p] = s4[p];
        }
        __syncthreads();

#pragma unroll 4
        for (int j = 0; j < 64; ++j) {
            float4 wa = *(const float4*)(sWb + j * 64 + c0);
            float4 wb = *(const float4*)(sWb + j * 64 + c0 + 4);
            float w[8] = {wa.x, wa.y, wa.z, wa.w, wb.x, wb.y, wb.z, wb.w};
            const float* sAj = sA + n0 * SA_LD + j;
#pragma unroll
            for (int i = 0; i < 8; ++i) {
                float a = sAj[i * 4 * SA_LD];
#pragma unroll
                for (int q = 0; q < 8; ++q) acc[i][q] = fmaf(a, w[q], acc[i][q]);
            }
        }
    }

    // Stage hidden = lrelu(conv1) into per-branch smem buffers
    __syncthreads();
    {
        float* dst = b ? sB : sA;
#pragma unroll
        for (int i = 0; i < 8; ++i) {
            float4 v0, v1;
            v0.x = lrelu(acc[i][0]); v0.y = lrelu(acc[i][1]);
            v0.z = lrelu(acc[i][2]); v0.w = lrelu(acc[i][3]);
            v1.x = lrelu(acc[i][4]); v1.y = lrelu(acc[i][5]);
            v1.z = lrelu(acc[i][6]); v1.w = lrelu(acc[i][7]);
            float* p = dst + (n0 + i * 4) * SA_LD + c0;
            *(float4*)p = v0;
            *(float4*)(p + 4) = v1;
        }
    }
    __syncthreads();

    // Second (dense) GEMM: hidden @ W2, W2 read from global (L1-resident, 16KB)
    const float* hid = b ? sB : sA;
    const float* w2  = b ? w2h : w2g;
#pragma unroll
    for (int i = 0; i < 8; ++i)
#pragma unroll
        for (int q = 0; q < 8; ++q) acc[i][q] = 0.f;

#pragma unroll 4
    for (int j = 0; j < 64; ++j) {
        float4 wa = *(const float4*)(w2 + j * 64 + c0);
        float4 wb = *(const float4*)(w2 + j * 64 + c0 + 4);
        float w[8] = {wa.x, wa.y, wa.z, wa.w, wb.x, wb.y, wb.z, wb.w};
        const float* hj = hid + n0 * SA_LD + j;
#pragma unroll
        for (int i = 0; i < 8; ++i) {
            float a = hj[i * 4 * SA_LD];
#pragma unroll
            for (int q = 0; q < 8; ++q) acc[i][q] = fmaf(a, w[q], acc[i][q]);
        }
    }

    // Store lrelu(hidden2) to the branch output (dense N x 64)
    {
        float* outp = b ? outh : outg;
#pragma unroll
        for (int i = 0; i < 8; ++i) {
            int n = nbase + n0 + i * 4;
            if (n < N) {
                float4 v0, v1;
                v0.x = lrelu(acc[i][0]); v0.y = lrelu(acc[i][1]);
                v0.z = lrelu(acc[i][2]); v0.w = lrelu(acc[i][3]);
                v1.x = lrelu(acc[i][4]); v1.y = lrelu(acc[i][5]);
                v1.z = lrelu(acc[i][6]); v1.w = lrelu(acc[i][7]);
                float* p = outp + (size_t)n * 64 + c0;
                *(float4*)p = v0;
                *(float4*)(p + 4) = v1;
            }
        }
    }
}

// ---------------------------------------------------------------------------
// Kernel B:
//   G = sum_k gather(srcg, idx_k) @ W3g[k]
//   H = sum_k gather(srch, idx_k) @ W3h[k]
//   out[n, c] = xpart[n, c] * exp(CLAMP * tanh(G/2)) + H
// srcg/srch are dense N x 64; xpart/out have row stride 128 (pre-offset cols).
// ---------------------------------------------------------------------------
__global__ __launch_bounds__(256, 2)
void kconvB(const float* __restrict__ srcg, const float* __restrict__ srch,
            const int* __restrict__ idx,
            const float* __restrict__ w3g, const float* __restrict__ w3h,
            const float* __restrict__ xpart,
            float* __restrict__ outp, int N)
{
    extern __shared__ float sm[];
    float* sA = sm;                     // gather_g / (unused late)
    float* sB = sm + TM * SA_LD;        // gather_h / H staging
    float* sW = sm + 2 * TM * SA_LD;    // W3 tiles

    const int t    = threadIdx.x;
    const int lane = t & 31;
    const int warp = t >> 5;
    const int b    = warp >> 2;
    const int wl   = warp & 3;
    const int c0   = (lane & 7) * 8;
    const int g    = lane >> 3;
    const int n0   = wl * 32 + g;
    const int nbase = blockIdx.x * TM;

    const int gr = t >> 1;
    const int gh = t & 1;

    int gn = nbase + gr;
    if (gn >= N) gn = N - 1;
    const int* idxRow = idx + (size_t)gn * KNB;

    float acc[8][8];
#pragma unroll
    for (int i = 0; i < 8; ++i)
#pragma unroll
        for (int q = 0; q < 8; ++q) acc[i][q] = 0.f;

    const float* sWb = sW + b * 4096;
    const float* sAb = b ? sB : sA;

    for (int k = 0; k < KNB; ++k) {
        __syncthreads();
        {
            const float4* wg4 = (const float4*)(w3g + (size_t)k * 4096);
            const float4* wh4 = (const float4*)(w3h + (size_t)k * 4096);
            float4* sg4 = (float4*)sW;
            float4* sh4 = (float4*)(sW + 4096);
#pragma unroll
            for (int i = 0; i < 4; ++i) {
                sg4[t + i * 256] = wg4[t + i * 256];
                sh4[t + i * 256] = wh4[t + i * 256];
            }
        }
        {
            const int row = idxRow[k];
            const float4* sg = (const float4*)(srcg + (size_t)row * 64) + gh * 8;
            const float4* sh = (const float4*)(srch + (size_t)row * 64) + gh * 8;
            float4* dg = (float4*)(sA + gr * SA_LD) + gh * 8;
            float4* dh = (float4*)(sB + gr * SA_LD) + gh * 8;
#pragma unroll
            for (int p = 0; p < 8; ++p) dg[p] = sg[p];
#pragma unroll
            for (int p = 0; p < 8; ++p) dh[p] = sh[p];
        }
        __syncthreads();

#pragma unroll 4
        for (int j = 0; j < 64; ++j) {
            float4 wa = *(const float4*)(sWb + j * 64 + c0);
            float4 wb = *(const float4*)(sWb + j * 64 + c0 + 4);
            float w[8] = {wa.x, wa.y, wa.z, wa.w, wb.x, wb.y, wb.z, wb.w};
            const float* sAj = sAb + n0 * SA_LD + j;
#pragma unroll
            for (int i = 0; i < 8; ++i) {
                float a = sAj[i * 4 * SA_LD];
#pragma unroll
                for (int q = 0; q < 8; ++q) acc[i][q] = fmaf(a, w[q], acc[i][q]);
            }
        }
    }

    // Epilogue: h-warps publish H into sB; g-warps combine and store.
    __syncthreads();
    if (b == 1) {
#pragma unroll
        for (int i = 0; i < 8; ++i) {
            float* p = sB + (n0 + i * 4) * SA_LD + c0;
            float4 v0, v1;
            v0.x = acc[i][0]; v0.y = acc[i][1]; v0.z = acc[i][2]; v0.w = acc[i][3];
            v1.x = acc[i][4]; v1.y = acc[i][5]; v1.z = acc[i][6]; v1.w = acc[i][7];
            *(float4*)p = v0;
            *(float4*)(p + 4) = v1;
        }
    }
    __syncthreads();
    if (b == 0) {
#pragma unroll
        for (int i = 0; i < 8; ++i) {
            const int nl = n0 + i * 4;
            const int n  = nbase + nl;
            if (n >= N) continue;
            const float* hp = sB + nl * SA_LD + c0;
            float4 h0 = *(const float4*)hp;
            float4 h1 = *(const float4*)(hp + 4);
            const float* xp = xpart + (size_t)n * 128 + c0;
            float4 x0 = *(const float4*)xp;
            float4 x1 = *(const float4*)(xp + 4);
            float s[8];
#pragma unroll
            for (int q = 0; q < 8; ++q)
                s[q] = expf(CLAMP_C * tanhf(0.5f * acc[i][q]));
            float4 y0, y1;
            y0.x = fmaf(x0.x, s[0], h0.x);
            y0.y = fmaf(x0.y, s[1], h0.y);
            y0.z = fmaf(x0.z, s[2], h0.z);
            y0.w = fmaf(x0.w, s[3], h0.w);
            y1.x = fmaf(x1.x, s[4], h1.x);
            y1.y = fmaf(x1.y, s[5], h1.y);
            y1.z = fmaf(x1.z, s[6], h1.z);
            y1.w = fmaf(x1.w, s[7], h1.w);
            float* op = outp + (size_t)n * 128 + c0;
            *(float4*)op = y0;
            *(float4*)(op + 4) = y1;
        }
    }
}

// ---------------------------------------------------------------------------
extern "C" void kernel_launch(void* const* d_in, const int* in_sizes, int n_in,
                              void* d_out, int out_size)
{
    const float* x     = (const float*)d_in[0];
    const int*   nbr   = (const int*)d_in[1];
    const float* g1_w1 = (const float*)d_in[2];
    const float* g1_w2 = (const float*)d_in[3];
    const float* g1_w3 = (const float*)d_in[4];
    const float* g2_w1 = (const float*)d_in[5];
    const float* g2_w2 = (const float*)d_in[6];
    const float* g2_w3 = (const float*)d_in[7];
    const float* h1_w1 = (const float*)d_in[8];
    const float* h1_w2 = (const float*)d_in[9];
    const float* h1_w3 = (const float*)d_in[10];
    const float* h2_w1 = (const float*)d_in[11];
    const float* h2_w2 = (const float*)d_in[12];
    const float* h2_w3 = (const float*)d_in[13];
    float* out = (float*)d_out;

    const int N = in_sizes[1] / KNB;
    const int blocks = (N + TM - 1) / TM;
    const size_t smem = (size_t)(2 * TM * SA_LD + 2 * 4096) * sizeof(float);

    cudaFuncSetAttribute(kconvA, cudaFuncAttributeMaxDynamicSharedMemorySize, (int)smem);
    cudaFuncSetAttribute(kconvB, cudaFuncAttributeMaxDynamicSharedMemorySize, (int)smem);

    float *hg_p = nullptr, *hh_p = nullptr;
    cudaGetSymbolAddress((void**)&hg_p, g_hg);
    cudaGetSymbolAddress((void**)&hh_p, g_hh);

    // Stage 1: s1/H from x2 (cols 64..127 of x), shared gather for g2 & h2.
    kconvA<<<blocks, 256, smem>>>(x + 64, 128, nbr,
                                  g2_w1, g2_w2, h2_w1, h2_w2,
                                  hg_p, hh_p, N);
    // y1 = x1 * exp(tanh(G/2)) + H  -> out[:, 0:64]
    kconvB<<<blocks, 256, smem>>>(hg_p, hh_p, nbr, g2_w3, h2_w3,
                                  x /*x1*/, out /*y1*/, N);
    // Stage 2: on y1 (out, stride 128), weights g1 & h1.
    kconvA<<<blocks, 256, smem>>>(out, 128, nbr,
                                  g1_w1, g1_w2, h1_w1, h1_w2,
                                  hg_p, hh_p, N);
    // y2 = x2 * exp(tanh(G2/2)) + H2 -> out[:, 64:128]
    kconvB<<<blocks, 256, smem>>>(hg_p, hh_p, nbr, g1_w3, h1_w3,
                                  x + 64 /*x2*/, out + 64 /*y2*/, N);
}

// round 2
// speedup vs baseline: 1.1156x; 1.1156x over previous
#include <cuda_runtime.h>
#include <math.h>

// Tile / problem constants
#define TM      128        // nodes per block
#define SA_LD   68         // padded smem row stride (floats), conflict-free
#define KNB     27         // neighbors
#define CLAMP_C 1.0f
#define MAXN    150000

typedef unsigned long long u64;

// Scratch for the hidden activations of the two branches (g / h).
__device__ float g_hg[(size_t)MAXN * 64];
__device__ float g_hh[(size_t)MAXN * 64];

__device__ __forceinline__ float lrelu(float v) { return v >= 0.f ? v : 0.2f * v; }

// Packed f32x2 FMA (SASS FFMA2) — 2 fp32 FMAs per instruction.
__device__ __forceinline__ void ffma2(u64& d, u64 a, u64 b) {
    asm("fma.rn.f32x2 %0, %1, %2, %0;" : "+l"(d) : "l"(a), "l"(b));
}
__device__ __forceinline__ u64 dup2(float x) {
    u64 r; asm("mov.b64 %0, {%1, %1};" : "=l"(r) : "f"(x)); return r;
}
__device__ __forceinline__ float2 unpk(u64 v) {
    float2 r; asm("mov.b64 {%0, %1}, %2;" : "=f"(r.x), "=f"(r.y) : "l"(v)); return r;
}

// Inner 64x(8-node x 8-channel) f32x2 outer-product accumulation.
//   actp: activation tile base for this thread's first node (stride SA_LD, rows +4*SA_LD)
//   wp:   weight matrix (64x64 row-major), thread reads cols c0..c0+7
// acc[i][p]: node i (rows n0+4i), channel pair p (c0+2p, c0+2p+1)
template <typename WPtr>
__device__ __forceinline__ void gemm_tile(const float* __restrict__ actp,
                                          WPtr wp, int c0, u64 acc[8][4])
{
#pragma unroll
    for (int j4 = 0; j4 < 64; j4 += 4) {
        float av[8][4];
#pragma unroll
        for (int i = 0; i < 8; ++i) {
            float4 t = *(const float4*)(actp + i * 4 * SA_LD + j4);
            av[i][0] = t.x; av[i][1] = t.y; av[i][2] = t.z; av[i][3] = t.w;
        }
#pragma unroll
        for (int jj = 0; jj < 4; ++jj) {
            const u64* wrow = (const u64*)(wp + (j4 + jj) * 64 + c0);
            ulonglong2 wA = *(const ulonglong2*)(wrow);
            ulonglong2 wB = *(const ulonglong2*)(wrow + 2);
#pragma unroll
            for (int i = 0; i < 8; ++i) {
                u64 a2 = dup2(av[i][jj]);
                ffma2(acc[i][0], a2, wA.x);
                ffma2(acc[i][1], a2, wA.y);
                ffma2(acc[i][2], a2, wB.x);
                ffma2(acc[i][3], a2, wB.y);
            }
        }
    }
}

// ---------------------------------------------------------------------------
// Kernel A: for both branches b in {g, h}:
//   hidden_b = lrelu( lrelu( sum_k gather(src, idx_k) @ W1_b[k] ) @ W2_b )
// Gather of `src` is shared between the two branches.
// ---------------------------------------------------------------------------
__global__ __launch_bounds__(256, 2)
void kconvA(const float* __restrict__ src, int src_ld,
            const int* __restrict__ idx,
            const float* __restrict__ w1g, const float* __restrict__ w2g,
            const float* __restrict__ w1h, const float* __restrict__ w2h,
            float* __restrict__ outg, float* __restrict__ outh, int N)
{
    extern __shared__ float sm[];
    float* sA = sm;                     // gathered tile / hidden_g
    float* sB = sm + TM * SA_LD;        // hidden_h staging
    float* sW = sm + 2 * TM * SA_LD;    // W1 tiles (g then h)

    const int t    = threadIdx.x;
    const int lane = t & 31;
    const int warp = t >> 5;
    const int b    = warp >> 2;         // 0 = g branch, 1 = h branch
    const int wl   = warp & 3;
    const int c0   = (lane & 7) * 8;
    const int g    = lane >> 3;
    const int n0   = wl * 32 + g;
    const int nbase = blockIdx.x * TM;

    const int gr = t >> 1;
    const int gh = t & 1;

    int gn = nbase + gr;
    if (gn >= N) gn = N - 1;
    const int* idxRow = idx + (size_t)gn * KNB;

    u64 acc[8][4];
#pragma unroll
    for (int i = 0; i < 8; ++i)
#pragma unroll
        for (int p = 0; p < 4; ++p) acc[i][p] = 0ull;

    const float* sWb  = sW + b * 4096;
    const float* actp = sA + n0 * SA_LD;

    for (int k = 0; k < KNB; ++k) {
        __syncthreads();
        {   // Stage W1[k] for both branches
            const float4* wg4 = (const float4*)(w1g + (size_t)k * 4096);
            const float4* wh4 = (const float4*)(w1h + (size_t)k * 4096);
            float4* sg4 = (float4*)sW;
            float4* sh4 = (float4*)(sW + 4096);
#pragma unroll
            for (int i = 0; i < 4; ++i) {
                sg4[t + i * 256] = wg4[t + i * 256];
                sh4[t + i * 256] = wh4[t + i * 256];
            }
        }
        {   // Gather 128 neighbor rows into sA
            const int row = idxRow[k];
            const float4* s4 = (const float4*)(src + (size_t)row * src_ld) + gh * 8;
            float4* d4 = (float4*)(sA + gr * SA_LD) + gh * 8;
#pragma unroll
            for (int p = 0; p < 8; ++p) d4[p] = s4[p];
        }
        __syncthreads();
        gemm_tile(actp, sWb, c0, acc);
    }

    // hidden = lrelu(conv1) staged to per-branch smem
    __syncthreads();
    {
        float* dst = b ? sB : sA;
#pragma unroll
        for (int i = 0; i < 8; ++i) {
            float2 p0 = unpk(acc[i][0]), p1 = unpk(acc[i][1]);
            float2 p2 = unpk(acc[i][2]), p3 = unpk(acc[i][3]);
            float4 v0 = make_float4(lrelu(p0.x), lrelu(p0.y), lrelu(p1.x), lrelu(p1.y));
            float4 v1 = make_float4(lrelu(p2.x), lrelu(p2.y), lrelu(p3.x), lrelu(p3.y));
            float* p = dst + (n0 + i * 4) * SA_LD + c0;
            *(float4*)p = v0;
            *(float4*)(p + 4) = v1;
        }
    }
    __syncthreads();

    // Second (dense) GEMM: hidden @ W2 (W2 streamed from global / L1)
    const float* hid = (b ? sB : sA) + n0 * SA_LD;
    const float* w2  = b ? w2h : w2g;
#pragma unroll
    for (int i = 0; i < 8; ++i)
#pragma unroll
        for (int p = 0; p < 4; ++p) acc[i][p] = 0ull;

    gemm_tile(hid, w2, c0, acc);

    // Store lrelu(hidden2) to branch output (dense N x 64)
    {
        float* outp = b ? outh : outg;
#pragma unroll
        for (int i = 0; i < 8; ++i) {
            int n = nbase + n0 + i * 4;
            if (n < N) {
                float2 p0 = unpk(acc[i][0]), p1 = unpk(acc[i][1]);
                float2 p2 = unpk(acc[i][2]), p3 = unpk(acc[i][3]);
                float4 v0 = make_float4(lrelu(p0.x), lrelu(p0.y), lrelu(p1.x), lrelu(p1.y));
                float4 v1 = make_float4(lrelu(p2.x), lrelu(p2.y), lrelu(p3.x), lrelu(p3.y));
                float* p = outp + (size_t)n * 64 + c0;
                *(float4*)p = v0;
                *(float4*)(p + 4) = v1;
            }
        }
    }
}

// ---------------------------------------------------------------------------
// Kernel B:
//   G = sum_k gather(srcg, idx_k) @ W3g[k]
//   H = sum_k gather(srch, idx_k) @ W3h[k]
//   out[n, c] = xpart[n, c] * exp(CLAMP * tanh(G/2)) + H
// ---------------------------------------------------------------------------
__global__ __launch_bounds__(256, 2)
void kconvB(const float* __restrict__ srcg, const float* __restrict__ srch,
            const int* __restrict__ idx,
            const float* __restrict__ w3g, const float* __restrict__ w3h,
            const float* __restrict__ xpart,
            float* __restrict__ outp, int N)
{
    extern __shared__ float sm[];
    float* sA = sm;
    float* sB = sm + TM * SA_LD;
    float* sW = sm + 2 * TM * SA_LD;

    const int t    = threadIdx.x;
    const int lane = t & 31;
    const int warp = t >> 5;
    const int b    = warp >> 2;
    const int wl   = warp & 3;
    const int c0   = (lane & 7) * 8;
    const int g    = lane >> 3;
    const int n0   = wl * 32 + g;
    const int nbase = blockIdx.x * TM;

    const int gr = t >> 1;
    const int gh = t & 1;

    int gn = nbase + gr;
    if (gn >= N) gn = N - 1;
    const int* idxRow = idx + (size_t)gn * KNB;

    u64 acc[8][4];
#pragma unroll
    for (int i = 0; i < 8; ++i)
#pragma unroll
        for (int p = 0; p < 4; ++p) acc[i][p] = 0ull;

    const float* sWb  = sW + b * 4096;
    const float* actp = (b ? sB : sA) + n0 * SA_LD;

    for (int k = 0; k < KNB; ++k) {
        __syncthreads();
        {
            const float4* wg4 = (const float4*)(w3g + (size_t)k * 4096);
            const float4* wh4 = (const float4*)(w3h + (size_t)k * 4096);
            float4* sg4 = (float4*)sW;
            float4* sh4 = (float4*)(sW + 4096);
#pragma unroll
            for (int i = 0; i < 4; ++i) {
                sg4[t + i * 256] = wg4[t + i * 256];
                sh4[t + i * 256] = wh4[t + i * 256];
            }
        }
        {
            const int row = idxRow[k];
            const float4* sg = (const float4*)(srcg + (size_t)row * 64) + gh * 8;
            const float4* sh = (const float4*)(srch + (size_t)row * 64) + gh * 8;
            float4* dg = (float4*)(sA + gr * SA_LD) + gh * 8;
            float4* dh = (float4*)(sB + gr * SA_LD) + gh * 8;
#pragma unroll
            for (int p = 0; p < 8; ++p) dg[p] = sg[p];
#pragma unroll
            for (int p = 0; p < 8; ++p) dh[p] = sh[p];
        }
        __syncthreads();
        gemm_tile(actp, sWb, c0, acc);
    }

    // Epilogue: h-warps publish H into sB; g-warps combine and store.
    __syncthreads();
    if (b == 1) {
#pragma unroll
        for (int i = 0; i < 8; ++i) {
            float2 p0 = unpk(acc[i][0]), p1 = unpk(acc[i][1]);
            float2 p2 = unpk(acc[i][2]), p3 = unpk(acc[i][3]);
            float* p = sB + (n0 + i * 4) * SA_LD + c0;
            *(float4*)p       = make_float4(p0.x, p0.y, p1.x, p1.y);
            *(float4*)(p + 4) = make_float4(p2.x, p2.y, p3.x, p3.y);
        }
    }
    __syncthreads();
    if (b == 0) {
#pragma unroll
        for (int i = 0; i < 8; ++i) {
            const int nl = n0 + i * 4;
            const int n  = nbase + nl;
            if (n >= N) continue;
            const float* hp = sB + nl * SA_LD + c0;
            float4 h0 = *(const float4*)hp;
            float4 h1 = *(const float4*)(hp + 4);
            const float* xp = xpart + (size_t)n * 128 + c0;
            float4 x0 = *(const float4*)xp;
            float4 x1 = *(const float4*)(xp + 4);
            float gv[8];
            {
                float2 p0 = unpk(acc[i][0]), p1 = unpk(acc[i][1]);
                float2 p2 = unpk(acc[i][2]), p3 = unpk(acc[i][3]);
                gv[0] = p0.x; gv[1] = p0.y; gv[2] = p1.x; gv[3] = p1.y;
                gv[4] = p2.x; gv[5] = p2.y; gv[6] = p3.x; gv[7] = p3.y;
            }
            float s[8];
#pragma unroll
            for (int q = 0; q < 8; ++q)
                s[q] = expf(CLAMP_C * tanhf(0.5f * gv[q]));
            float4 y0, y1;
            y0.x = fmaf(x0.x, s[0], h0.x);
            y0.y = fmaf(x0.y, s[1], h0.y);
            y0.z = fmaf(x0.z, s[2], h0.z);
            y0.w = fmaf(x0.w, s[3], h0.w);
            y1.x = fmaf(x1.x, s[4], h1.x);
            y1.y = fmaf(x1.y, s[5], h1.y);
            y1.z = fmaf(x1.z, s[6], h1.z);
            y1.w = fmaf(x1.w, s[7], h1.w);
            float* op = outp + (size_t)n * 128 + c0;
            *(float4*)op = y0;
            *(float4*)(op + 4) = y1;
        }
    }
}

// ---------------------------------------------------------------------------
extern "C" void kernel_launch(void* const* d_in, const int* in_sizes, int n_in,
                              void* d_out, int out_size)
{
    const float* x     = (const float*)d_in[0];
    const int*   nbr   = (const int*)d_in[1];
    const float* g1_w1 = (const float*)d_in[2];
    const float* g1_w2 = (const float*)d_in[3];
    const float* g1_w3 = (const float*)d_in[4];
    const float* g2_w1 = (const float*)d_in[5];
    const float* g2_w2 = (const float*)d_in[6];
    const float* g2_w3 = (const float*)d_in[7];
    const float* h1_w1 = (const float*)d_in[8];
    const float* h1_w2 = (const float*)d_in[9];
    const float* h1_w3 = (const float*)d_in[10];
    const float* h2_w1 = (const float*)d_in[11];
    const float* h2_w2 = (const float*)d_in[12];
    const float* h2_w3 = (const float*)d_in[13];
    float* out = (float*)d_out;

    const int N = in_sizes[1] / KNB;
    const int blocks = (N + TM - 1) / TM;
    const size_t smem = (size_t)(2 * TM * SA_LD + 2 * 4096) * sizeof(float);

    cudaFuncSetAttribute(kconvA, cudaFuncAttributeMaxDynamicSharedMemorySize, (int)smem);
    cudaFuncSetAttribute(kconvB, cudaFuncAttributeMaxDynamicSharedMemorySize, (int)smem);

    float *hg_p = nullptr, *hh_p = nullptr;
    cudaGetSymbolAddress((void**)&hg_p, g_hg);
    cudaGetSymbolAddress((void**)&hh_p, g_hh);

    // Stage 1: bottlenecks g2/h2 on x2 (cols 64..127), shared gather.
    kconvA<<<blocks, 256, smem>>>(x + 64, 128, nbr,
                                  g2_w1, g2_w2, h2_w1, h2_w2,
                                  hg_p, hh_p, N);
    // y1 = x1 * exp(tanh(G/2)) + H  -> out[:, 0:64]
    kconvB<<<blocks, 256, smem>>>(hg_p, hh_p, nbr, g2_w3, h2_w3,
                                  x /*x1*/, out /*y1*/, N);
    // Stage 2: bottlenecks g1/h1 on y1 (out, stride 128).
    kconvA<<<blocks, 256, smem>>>(out, 128, nbr,
                                  g1_w1, g1_w2, h1_w1, h1_w2,
                                  hg_p, hh_p, N);
    // y2 = x2 * exp(tanh(G2/2)) + H2 -> out[:, 64:128]
    kconvB<<<blocks, 256, smem>>>(hg_p, hh_p, nbr, g1_w3, h1_w3,
                                  x + 64 /*x2*/, out + 64 /*y2*/, N);
}

// round 4
// speedup vs baseline: 2.7322x; 2.4491x over previous
#include <cuda_runtime.h>
#include <cuda_bf16.h>
#include <math.h>
#include <stdint.h>

#define TM      128
#define KNB     27
#define MAXN    150000

// SMEM byte offsets (dynamic smem, 96KB/block)
#define OFF_AG   0            // A tile g: 128x64 bf16 hi (16KB)
#define OFF_AGL  16384        // A tile g lo
#define OFF_AH   32768        // A tile h hi
#define OFF_AHL  49152        // A tile h lo
#define OFF_W    65536        // 4 weight planes x 8KB: [g_hi, g_lo, h_hi, h_lo]
#define SMEM_BYTES 98304

// ------------------------- device scratch -------------------------
__device__ float g_hg[(size_t)MAXN * 64];
__device__ float g_hh[(size_t)MAXN * 64];
// 8 conv tensors (27 planes of 64x64), hi/lo split, pre-swizzled [kk][n]
__device__ __align__(16) __nv_bfloat16 g_wch[8 * 27 * 4096];
__device__ __align__(16) __nv_bfloat16 g_wcl[8 * 27 * 4096];
// 4 dense tensors (1 plane each)
__device__ __align__(16) __nv_bfloat16 g_wdh[4 * 4096];
__device__ __align__(16) __nv_bfloat16 g_wdl[4 * 4096];

// ------------------------- helpers -------------------------
__device__ __forceinline__ uint32_t smem_u32(const void* p) {
    uint32_t a;
    asm("{ .reg .u64 t; cvta.to.shared.u64 t, %1; cvt.u32.u64 %0, t; }" : "=r"(a) : "l"(p));
    return a;
}
__device__ __forceinline__ float lrelu(float v) { return v >= 0.f ? v : 0.2f * v; }

// pack two f32 -> bf16x2 (lo_elem in lower 16 bits)
__device__ __forceinline__ uint32_t pack_bf2(float lo_elem, float hi_elem) {
    uint32_t r;
    asm("cvt.rn.bf16x2.f32 %0, %1, %2;" : "=r"(r) : "f"(hi_elem), "f"(lo_elem));
    return r;
}
__device__ __forceinline__ float bflo_f(uint32_t u) { return __uint_as_float(u << 16); }
__device__ __forceinline__ float bfhi_f(uint32_t u) { return __uint_as_float(u & 0xFFFF0000u); }

__device__ __forceinline__ void ldsm4(uint32_t* r, uint32_t a) {
    asm volatile("ldmatrix.sync.aligned.m8n8.x4.shared.b16 {%0,%1,%2,%3}, [%4];"
                 : "=r"(r[0]), "=r"(r[1]), "=r"(r[2]), "=r"(r[3]) : "r"(a));
}
__device__ __forceinline__ void ldsm4t(uint32_t* r, uint32_t a) {
    asm volatile("ldmatrix.sync.aligned.m8n8.x4.trans.shared.b16 {%0,%1,%2,%3}, [%4];"
                 : "=r"(r[0]), "=r"(r[1]), "=r"(r[2]), "=r"(r[3]) : "r"(a));
}
__device__ __forceinline__ void mma_bf16(float* d, const uint32_t* a, const uint32_t* b) {
    asm volatile(
        "mma.sync.aligned.m16n8k16.row.col.f32.bf16.bf16.f32 "
        "{%0,%1,%2,%3}, {%4,%5,%6,%7}, {%8,%9}, {%0,%1,%2,%3};"
        : "+f"(d[0]), "+f"(d[1]), "+f"(d[2]), "+f"(d[3])
        : "r"(a[0]), "r"(a[1]), "r"(a[2]), "r"(a[3]), "r"(b[0]), "r"(b[1]));
}

// ------------------------- weight prep -------------------------
// B plane layout: [kk][n] (kk = input channel = MMA-k, n = output channel),
// 64x64 bf16, 128B rows, chunk(16B) index XOR-swizzled with (kk & 7).
__global__ void kprep_conv(const float* w0, const float* w1, const float* w2,
                           const float* w3, const float* w4, const float* w5,
                           const float* w6, const float* w7) {
    int e = blockIdx.x * 256 + threadIdx.x;
    const int per = 27 * 4096;
    if (e >= 8 * per) return;
    int ti = e / per;
    int r  = e % per;
    int k  = r >> 12;
    int p  = r & 4095;
    int kk = p >> 6;
    int n  = p & 63;
    const float* ws[8] = {w0, w1, w2, w3, w4, w5, w6, w7};
    float v = ws[ti][(size_t)k * 4096 + kk * 64 + n];
    __nv_bfloat16 bh = __float2bfloat16_rn(v);
    __nv_bfloat16 bl = __float2bfloat16_rn(v - __bfloat162float(bh));
    int off = kk * 128 + (((n >> 3) ^ (kk & 7)) << 4) + (n & 7) * 2;
    size_t base = ((size_t)ti * 27 + k) * 8192;
    *(__nv_bfloat16*)((char*)g_wch + base + off) = bh;
    *(__nv_bfloat16*)((char*)g_wcl + base + off) = bl;
}

__global__ void kprep_dense(const float* w0, const float* w1,
                            const float* w2, const float* w3) {
    int e = blockIdx.x * 256 + threadIdx.x;
    if (e >= 4 * 4096) return;
    int ti = e >> 12;
    int p  = e & 4095;
    int kk = p >> 6;
    int n  = p & 63;
    const float* ws[4] = {w0, w1, w2, w3};
    float v = ws[ti][kk * 64 + n];
    __nv_bfloat16 bh = __float2bfloat16_rn(v);
    __nv_bfloat16 bl = __float2bfloat16_rn(v - __bfloat162float(bh));
    int off = kk * 128 + (((n >> 3) ^ (kk & 7)) << 4) + (n & 7) * 2;
    size_t base = (size_t)ti * 8192;
    *(__nv_bfloat16*)((char*)g_wdh + base + off) = bh;
    *(__nv_bfloat16*)((char*)g_wdl + base + off) = bl;
}

// stage 4 pre-swizzled 8KB planes linearly into smem (256 threads)
__device__ __forceinline__ void stage4(char* dst,
    const __nv_bfloat16* p0, const __nv_bfloat16* p1,
    const __nv_bfloat16* p2, const __nv_bfloat16* p3, int t)
{
    float4* d = (float4*)dst;
    d[t]              = ((const float4*)p0)[t];
    d[t + 256]        = ((const float4*)p0)[t + 256];
    d[512 + t]        = ((const float4*)p1)[t];
    d[512 + t + 256]  = ((const float4*)p1)[t + 256];
    d[1024 + t]       = ((const float4*)p2)[t];
    d[1024 + t + 256] = ((const float4*)p2)[t + 256];
    d[1536 + t]       = ((const float4*)p3)[t];
    d[1536 + t + 256] = ((const float4*)p3)[t + 256];
}

// gather 128 rows of 64 f32, convert to bf16 hi/lo, store swizzled (256 thr)
__device__ __forceinline__ void gather_tile(char* sm, int offH, int offL,
    const float* __restrict__ src, int ld, const int* __restrict__ idx,
    int k, int nbase, int N, int t)
{
    int row = t >> 1, half = t & 1;
    int n = nbase + row; if (n >= N) n = N - 1;
    int g = idx[(size_t)n * KNB + k];
    const float4* s4 = (const float4*)(src + (size_t)g * ld) + half * 8;
#pragma unroll
    for (int c = 0; c < 4; ++c) {
        float4 v0 = s4[c * 2], v1 = s4[c * 2 + 1];
        int chunk = half * 4 + c;
        int sw = row * 128 + ((chunk ^ (row & 7)) << 4);
        uint32_t h0 = pack_bf2(v0.x, v0.y), h1 = pack_bf2(v0.z, v0.w);
        uint32_t h2 = pack_bf2(v1.x, v1.y), h3 = pack_bf2(v1.z, v1.w);
        uint32_t l0 = pack_bf2(v0.x - bflo_f(h0), v0.y - bfhi_f(h0));
        uint32_t l1 = pack_bf2(v0.z - bflo_f(h1), v0.w - bfhi_f(h1));
        uint32_t l2 = pack_bf2(v1.x - bflo_f(h2), v1.y - bfhi_f(h2));
        uint32_t l3 = pack_bf2(v1.z - bflo_f(h3), v1.w - bfhi_f(h3));
        *(uint4*)(sm + offH + sw) = make_uint4(h0, h1, h2, h3);
        *(uint4*)(sm + offL + sw) = make_uint4(l0, l1, l2, l3);
    }
}

// one 64-deep K chunk: warp computes 32 rows x 64 cols, split-bf16 (3 MMAs)
__device__ __forceinline__ void mma_block(float acc[2][8][4],
    uint32_t aHi, uint32_t aLo, uint32_t bHi, uint32_t bLo,
    int wl, int lr, int lc)
{
    const int arow = (wl * 32 + lr) * 128;   // A row byte offset (mt adds 2048)
    const int axor = lr & 7;
#pragma unroll
    for (int ks = 0; ks < 4; ++ks) {
        uint32_t ah[2][4], al[2][4];
        const int ac = ((ks * 2 + lc) ^ axor) << 4;
#pragma unroll
        for (int mt = 0; mt < 2; ++mt) {
            uint32_t ad = arow + mt * 2048 + ac;
            ldsm4(ah[mt], aHi + ad);
            ldsm4(al[mt], aLo + ad);
        }
        const int brow = ks * 2048 + lr * 128;
#pragma unroll
        for (int np = 0; np < 4; ++np) {
            uint32_t bd = brow + (((2 * np + lc) ^ axor) << 4);
            uint32_t bh[4], bl[4];
            ldsm4t(bh, bHi + bd);
            ldsm4t(bl, bLo + bd);
#pragma unroll
            for (int mt = 0; mt < 2; ++mt) {
#pragma unroll
                for (int j = 0; j < 2; ++j) {
                    float* d = acc[mt][np * 2 + j];
                    mma_bf16(d, ah[mt], &bh[j * 2]);
                    mma_bf16(d, al[mt], &bh[j * 2]);
                    mma_bf16(d, ah[mt], &bl[j * 2]);
                }
            }
        }
    }
}

// write accumulators (optionally lrelu'd) as bf16 hi/lo swizzled A tiles
__device__ __forceinline__ void acc_to_tiles(char* sm, int baseH, int baseL,
    float acc[2][8][4], int wl, int gID, int tig)
{
#pragma unroll
    for (int mt = 0; mt < 2; ++mt) {
        int r0 = wl * 32 + mt * 16 + gID;
        int r1 = r0 + 8;
#pragma unroll
        for (int nt = 0; nt < 8; ++nt) {
            float e0 = lrelu(acc[mt][nt][0]), e1 = lrelu(acc[mt][nt][1]);
            float e2 = lrelu(acc[mt][nt][2]), e3 = lrelu(acc[mt][nt][3]);
            uint32_t h0 = pack_bf2(e0, e1);
            uint32_t l0 = pack_bf2(e0 - bflo_f(h0), e1 - bfhi_f(h0));
            uint32_t h1 = pack_bf2(e2, e3);
            uint32_t l1 = pack_bf2(e2 - bflo_f(h1), e3 - bfhi_f(h1));
            int b0 = r0 * 128 + ((nt ^ (r0 & 7)) << 4) + tig * 4;
            int b1 = r1 * 128 + ((nt ^ (r1 & 7)) << 4) + tig * 4;
            *(uint32_t*)(sm + baseH + b0) = h0;
            *(uint32_t*)(sm + baseL + b0) = l0;
            *(uint32_t*)(sm + baseH + b1) = h1;
            *(uint32_t*)(sm + baseL + b1) = l1;
        }
    }
}

// ---------------------------------------------------------------------------
// kconvA: hidden_b = lrelu( lrelu( sum_k gather(src) @ W1_b[k] ) @ W2_b ),
// b in {g,h}, shared gather. Warps 0-3: g, 4-7: h. Outputs dense N x 64 f32.
// ---------------------------------------------------------------------------
__global__ __launch_bounds__(256, 2)
void kconvA_mma(const float* __restrict__ src, int ld,
                const int* __restrict__ idx,
                const __nv_bfloat16* w1gh, const __nv_bfloat16* w1gl,
                const __nv_bfloat16* w1hh, const __nv_bfloat16* w1hl,
                const __nv_bfloat16* w2gh, const __nv_bfloat16* w2gl,
                const __nv_bfloat16* w2hh, const __nv_bfloat16* w2hl,
                float* __restrict__ outg, float* __restrict__ outh, int N)
{
    extern __shared__ char sm[];
    const uint32_t sb = smem_u32(sm);
    const int t = threadIdx.x;
    const int lane = t & 31, w = t >> 5;
    const int b = w >> 2, wl = w & 3;
    const int lr = ((lane >> 3) & 1) * 8 + (lane & 7);
    const int lc = lane >> 4;
    const int gID = lane >> 2, tig = lane & 3;
    const int nbase = blockIdx.x * TM;

    float acc[2][8][4];
#pragma unroll
    for (int mt = 0; mt < 2; ++mt)
#pragma unroll
        for (int nt = 0; nt < 8; ++nt)
#pragma unroll
            for (int q = 0; q < 4; ++q) acc[mt][nt][q] = 0.f;

    const uint32_t bHi = sb + OFF_W + b * 16384, bLo = bHi + 8192;

    for (int k = 0; k < KNB; ++k) {
        __syncthreads();
        stage4(sm + OFF_W, w1gh + k * 4096, w1gl + k * 4096,
                           w1hh + k * 4096, w1hl + k * 4096, t);
        gather_tile(sm, OFF_AG, OFF_AGL, src, ld, idx, k, nbase, N, t);
        __syncthreads();
        mma_block(acc, sb + OFF_AG, sb + OFF_AGL, bHi, bLo, wl, lr, lc);
    }

    // hidden = lrelu(conv1) -> per-branch bf16 tiles; stage W2 planes
    __syncthreads();
    acc_to_tiles(sm, b ? OFF_AH : OFF_AG, b ? OFF_AHL : OFF_AGL, acc, wl, gID, tig);
    stage4(sm + OFF_W, w2gh, w2gl, w2hh, w2hl, t);
    __syncthreads();

#pragma unroll
    for (int mt = 0; mt < 2; ++mt)
#pragma unroll
        for (int nt = 0; nt < 8; ++nt)
#pragma unroll
            for (int q = 0; q < 4; ++q) acc[mt][nt][q] = 0.f;

    mma_block(acc, sb + (b ? OFF_AH : OFF_AG), sb + (b ? OFF_AHL : OFF_AGL),
              bHi, bLo, wl, lr, lc);

    // store lrelu(hidden2) f32 to branch output (dense N x 64)
    float* outp = b ? outh : outg;
#pragma unroll
    for (int mt = 0; mt < 2; ++mt) {
        int n0 = nbase + wl * 32 + mt * 16 + gID;
        int n1 = n0 + 8;
#pragma unroll
        for (int nt = 0; nt < 8; ++nt) {
            int c = nt * 8 + tig * 2;
            if (n0 < N)
                *(float2*)(outp + (size_t)n0 * 64 + c) =
                    make_float2(lrelu(acc[mt][nt][0]), lrelu(acc[mt][nt][1]));
            if (n1 < N)
                *(float2*)(outp + (size_t)n1 * 64 + c) =
                    make_float2(lrelu(acc[mt][nt][2]), lrelu(acc[mt][nt][3]));
        }
    }
}

// ---------------------------------------------------------------------------
// kconvB: G = sum_k gather(srcg) @ W3g[k], H = sum_k gather(srch) @ W3h[k]
// out[n,c] = xpart[n,c] * exp(tanh(G/2)) + H   (xpart/out row stride 128)
// ---------------------------------------------------------------------------
__global__ __launch_bounds__(256, 2)
void kconvB_mma(const float* __restrict__ srcg, const float* __restrict__ srch,
                const int* __restrict__ idx,
                const __nv_bfloat16* w3gh, const __nv_bfloat16* w3gl,
                const __nv_bfloat16* w3hh, const __nv_bfloat16* w3hl,
                const float* __restrict__ xpart,
                float* __restrict__ outp, int N)
{
    extern __shared__ char sm[];
    const uint32_t sb = smem_u32(sm);
    const int t = threadIdx.x;
    const int lane = t & 31, w = t >> 5;
    const int b = w >> 2, wl = w & 3;
    const int lr = ((lane >> 3) & 1) * 8 + (lane & 7);
    const int lc = lane >> 4;
    const int gID = lane >> 2, tig = lane & 3;
    const int nbase = blockIdx.x * TM;

    float acc[2][8][4];
#pragma unroll
    for (int mt = 0; mt < 2; ++mt)
#pragma unroll
        for (int nt = 0; nt < 8; ++nt)
#pragma unroll
            for (int q = 0; q < 4; ++q) acc[mt][nt][q] = 0.f;

    const uint32_t bHi = sb + OFF_W + b * 16384, bLo = bHi + 8192;
    const uint32_t aHi = sb + (b ? OFF_AH : OFF_AG);
    const uint32_t aLo = sb + (b ? OFF_AHL : OFF_AGL);

    for (int k = 0; k < KNB; ++k) {
        __syncthreads();
        stage4(sm + OFF_W, w3gh + k * 4096, w3gl + k * 4096,
                           w3hh + k * 4096, w3hl + k * 4096, t);
        gather_tile(sm, OFF_AG, OFF_AGL, srcg, 64, idx, k, nbase, N, t);
        gather_tile(sm, OFF_AH, OFF_AHL, srch, 64, idx, k, nbase, N, t);
        __syncthreads();
        mma_block(acc, aHi, aLo, bHi, bLo, wl, lr, lc);
    }

    // epilogue: h warps publish H f32 (stride-68) into smem; g warps combine
    __syncthreads();
    float* hs = (float*)sm;
    if (b == 1) {
#pragma unroll
        for (int mt = 0; mt < 2; ++mt) {
            int r0 = wl * 32 + mt * 16 + gID;
            int r1 = r0 + 8;
#pragma unroll
            for (int nt = 0; nt < 8; ++nt) {
                int c = nt * 8 + tig * 2;
                *(float2*)(hs + r0 * 68 + c) = make_float2(acc[mt][nt][0], acc[mt][nt][1]);
                *(float2*)(hs + r1 * 68 + c) = make_float2(acc[mt][nt][2], acc[mt][nt][3]);
            }
        }
    }
    __syncthreads();
    if (b == 0) {
#pragma unroll
        for (int mt = 0; mt < 2; ++mt) {
#pragma unroll
            for (int half = 0; half < 2; ++half) {
                int r = wl * 32 + mt * 16 + half * 8 + gID;
                int n = nbase + r;
                if (n >= N) continue;
#pragma unroll
                for (int nt = 0; nt < 8; ++nt) {
                    int c = nt * 8 + tig * 2;
                    float g0 = acc[mt][nt][half * 2 + 0];
                    float g1 = acc[mt][nt][half * 2 + 1];
                    float2 hv = *(const float2*)(hs + r * 68 + c);
                    float2 xv = *(const float2*)(xpart + (size_t)n * 128 + c);
                    float2 y;
                    y.x = fmaf(xv.x, expf(tanhf(0.5f * g0)), hv.x);
                    y.y = fmaf(xv.y, expf(tanhf(0.5f * g1)), hv.y);
                    *(float2*)(outp + (size_t)n * 128 + c) = y;
                }
            }
        }
    }
}

// ---------------------------------------------------------------------------
extern "C" void kernel_launch(void* const* d_in, const int* in_sizes, int n_in,
                              void* d_out, int out_size)
{
    const float* x     = (const float*)d_in[0];
    const int*   nbr   = (const int*)d_in[1];
    const float* g1_w1 = (const float*)d_in[2];
    const float* g1_w2 = (const float*)d_in[3];
    const float* g1_w3 = (const float*)d_in[4];
    const float* g2_w1 = (const float*)d_in[5];
    const float* g2_w2 = (const float*)d_in[6];
    const float* g2_w3 = (const float*)d_in[7];
    const float* h1_w1 = (const float*)d_in[8];
    const float* h1_w2 = (const float*)d_in[9];
    const float* h1_w3 = (const float*)d_in[10];
    const float* h2_w1 = (const float*)d_in[11];
    const float* h2_w2 = (const float*)d_in[12];
    const float* h2_w3 = (const float*)d_in[13];
    float* out = (float*)d_out;

    const int N = in_sizes[1] / KNB;
    const int blocks = (N + TM - 1) / TM;

    cudaFuncSetAttribute(kconvA_mma, cudaFuncAttributeMaxDynamicSharedMemorySize, SMEM_BYTES);
    cudaFuncSetAttribute(kconvB_mma, cudaFuncAttributeMaxDynamicSharedMemorySize, SMEM_BYTES);

    float *hg, *hh;
    cudaGetSymbolAddress((void**)&hg, g_hg);
    cudaGetSymbolAddress((void**)&hh, g_hh);
    __nv_bfloat16 *wch, *wcl, *wdh, *wdl;
    cudaGetSymbolAddress((void**)&wch, g_wch);
    cudaGetSymbolAddress((void**)&wcl, g_wcl);
    cudaGetSymbolAddress((void**)&wdh, g_wdh);
    cudaGetSymbolAddress((void**)&wdl, g_wdl);

    // conv tensor order: 0:g2w1 1:h2w1 2:g2w3 3:h2w3 4:g1w1 5:h1w1 6:g1w3 7:h1w3
    kprep_conv<<<(8 * 27 * 4096 + 255) / 256, 256>>>(
        g2_w1, h2_w1, g2_w3, h2_w3, g1_w1, h1_w1, g1_w3, h1_w3);
    // dense order: 0:g2w2 1:h2w2 2:g1w2 3:h1w2
    kprep_dense<<<(4 * 4096 + 255) / 256, 256>>>(g2_w2, h2_w2, g1_w2, h1_w2);

    const int CP = 27 * 4096;

    // Stage 1: bottlenecks g2/h2 on x2 (cols 64..127 of x, stride 128)
    kconvA_mma<<<blocks, 256, SMEM_BYTES>>>(
        x + 64, 128, nbr,
        wch + 0 * CP, wcl + 0 * CP, wch + 1 * CP, wcl + 1 * CP,
        wdh + 0 * 4096, wdl + 0 * 4096, wdh + 1 * 4096, wdl + 1 * 4096,
        hg, hh, N);
    // y1 = x1 * exp(tanh(G/2)) + H  -> out[:, 0:64]
    kconvB_mma<<<blocks, 256, SMEM_BYTES>>>(
        hg, hh, nbr,
        wch + 2 * CP, wcl + 2 * CP, wch + 3 * CP, wcl + 3 * CP,
        x /*x1*/, out /*y1*/, N);
    // Stage 2: bottlenecks g1/h1 on y1 (out, stride 128)
    kconvA_mma<<<blocks, 256, SMEM_BYTES>>>(
        out, 128, nbr,
        wch + 4 * CP, wcl + 4 * CP, wch + 5 * CP, wcl + 5 * CP,
        wdh + 2 * 4096, wdl + 2 * 4096, wdh + 3 * 4096, wdl + 3 * 4096,
        hg, hh, N);
    // y2 = x2 * exp(tanh(G2/2)) + H2 -> out[:, 64:128]
    kconvB_mma<<<blocks, 256, SMEM_BYTES>>>(
        hg, hh, nbr,
        wch + 6 * CP, wcl + 6 * CP, wch + 7 * CP, wcl + 7 * CP,
        x + 64 /*x2*/, out + 64 /*y2*/, N);
}